// round 1
// baseline (speedup 1.0000x reference)
#include <cuda_runtime.h>
#include <cuda_bf16.h>

// Problem constants
#define B_  4
#define N_  262144          // elements per batch (2^18)
#define F_  64
#define S_  1024            // NUM_SEG
#define OUT_ 64

// ---------------- device scratch (no allocations allowed) ----------------
// Accumulator block zeroed each call with one cudaMemsetAsync:
//   [0,        262144) sum_row  [B][1024][64]
//   [262144,   524288) sum_col  [B][1024][64]
//   [524288,   528384) cnt_row  [B][1024]
//   [528384,   532480) cnt_col  [B][1024]
#define ACCUM_SZ (2*B_*S_*F_ + 2*B_*S_)
__device__ __align__(256) float g_accum[ACCUM_SZ];
#define SUM_ROW (g_accum)
#define SUM_COL (g_accum + B_*S_*F_)
#define CNT_ROW (g_accum + 2*B_*S_*F_)
#define CNT_COL (g_accum + 2*B_*S_*F_ + B_*S_)

__device__ __align__(256) float g_M[4*F_*OUT_];      // M_self, M_row, M_col, M_glob
__device__ __align__(256) float g_bias_const[OUT_];  // b_self@Wo0+b_row@Wo1+b_col@Wo2+b_glob@Wo3+b_out
__device__ __align__(256) float g_rowvec[B_*S_*OUT_];
__device__ __align__(256) float g_colvec[B_*S_*OUT_];
__device__ __align__(256) float g_biasb[B_*OUT_];    // bias_const + gmean@M_glob, per batch

// ---------------- packed fp32x2 helpers (sm_103a FFMA2) ----------------
__device__ __forceinline__ unsigned long long pk2(float x) {
    unsigned long long r;
    asm("mov.b64 %0, {%1, %1};" : "=l"(r) : "f"(x));
    return r;
}
__device__ __forceinline__ void fma2(unsigned long long& d, unsigned long long a, unsigned long long b) {
    asm("fma.rn.f32x2 %0, %1, %2, %0;" : "+l"(d) : "l"(a), "l"(b));
}
__device__ __forceinline__ float2 up2(unsigned long long v) {
    float2 r;
    asm("mov.b64 {%0, %1}, %2;" : "=f"(r.x), "=f"(r.y) : "l"(v));
    return r;
}

// ---------------- K0: fold weight matrices ----------------
// M_m[f][o] = sum_j W_m[f][j] * W_out[m*64+j][o]
__global__ void prep_kernel(const float* __restrict__ Wself, const float* __restrict__ Wrow,
                            const float* __restrict__ Wcol,  const float* __restrict__ Wglob,
                            const float* __restrict__ Wout,
                            const float* __restrict__ bself, const float* __restrict__ brow,
                            const float* __restrict__ bcol,  const float* __restrict__ bglob,
                            const float* __restrict__ bout) {
    const int stride = blockDim.x * gridDim.x;
    const int tid = blockIdx.x * blockDim.x + threadIdx.x;
    for (int job = tid; job < 4 * F_ * OUT_; job += stride) {
        const int m = job >> 12;          // which matrix
        const int r = job & 4095;
        const int f = r >> 6, o = r & 63;
        const float* W = (m == 0) ? Wself : (m == 1) ? Wrow : (m == 2) ? Wcol : Wglob;
        float acc = 0.f;
        #pragma unroll 16
        for (int j = 0; j < 64; ++j)
            acc += W[f * 64 + j] * Wout[(m * 64 + j) * OUT_ + o];
        g_M[job] = acc;
    }
    for (int o = tid; o < OUT_; o += stride) {
        float acc = bout[o];
        for (int j = 0; j < 64; ++j) {
            acc += bself[j] * Wout[j * OUT_ + o];
            acc += brow [j] * Wout[(64  + j) * OUT_ + o];
            acc += bcol [j] * Wout[(128 + j) * OUT_ + o];
            acc += bglob[j] * Wout[(192 + j) * OUT_ + o];
        }
        g_bias_const[o] = acc;
    }
}

// ---------------- K1: scatter (segment sums + counts) ----------------
// 256 threads, 16 elements in flight (16 threads/element, one float4 each).
__global__ void __launch_bounds__(256) scatter_kernel(const float* __restrict__ value,
                                                      const int* __restrict__ index) {
    const int tid = threadIdx.x;
    const int c   = tid & 15;    // float4 chunk 0..15
    const int sub = tid >> 4;    // element slot 0..15
    const long long base = (long long)blockIdx.x * 256;
    for (int it = 0; it < 16; ++it) {
        const long long e = base + it * 16 + sub;
        const int b  = (int)(e >> 18);
        const int i0 = index[e * 2];
        const int i1 = index[e * 2 + 1];
        const float4 v = ((const float4*)(value + (e << 6)))[c];
        atomicAdd((float4*)(SUM_ROW + ((((long long)b << 10) + i0) << 6) + (c << 2)), v);
        atomicAdd((float4*)(SUM_COL + ((((long long)b << 10) + i1) << 6) + (c << 2)), v);
        if (c == 0) {
            atomicAdd(CNT_ROW + (b << 10) + i0, 1.0f);
            atomicAdd(CNT_COL + (b << 10) + i1, 1.0f);
        }
    }
}

// ---------------- K2: global-mean path -> per-batch bias ----------------
// gsum[b][f] = sum_s sum_row[b][s][f]; biasb[b][o] = bias_const[o] + (gsum/N)@M_glob
__global__ void gbias_kernel() {
    __shared__ float gmean[64];
    const int b = blockIdx.x, t = threadIdx.x;
    float acc = 0.f;
    const long long base = (long long)b * S_ * 64;
    for (int s = 0; s < S_; ++s) acc += SUM_ROW[base + s * 64 + t];
    gmean[t] = acc * (1.0f / (float)N_);
    __syncthreads();
    float bias = g_bias_const[t];
    #pragma unroll
    for (int f = 0; f < 64; ++f) bias += gmean[f] * g_M[3 * 4096 + f * 64 + t];
    g_biasb[b * 64 + t] = bias;
}

// ---------------- K3: per-segment pooled vectors ----------------
// rowvec[b][s] = (sum_row/(cnt+1e-9)) @ M_row ; colvec analogous.
// 128 blocks (B*32), each handles 32 segments with M_row/M_col cached in smem.
__global__ void __launch_bounds__(128) segvec_kernel() {
    __shared__ float Mr[4096];
    __shared__ float Mc[4096];
    __shared__ float meanr[64], meanc[64];
    const int tid = threadIdx.x;
    const int b = blockIdx.x >> 5;
    const int segbase = (blockIdx.x & 31) << 5;
    for (int i = tid; i < 4096; i += 128) { Mr[i] = g_M[4096 + i]; Mc[i] = g_M[8192 + i]; }
    __syncthreads();
    const int o = tid & 63;
    const bool isCol = tid >= 64;
    for (int s = 0; s < 32; ++s) {
        const int seg = segbase + s;
        const long long sb = (((long long)b << 10) + seg) << 6;
        if (tid < 64)
            meanr[tid] = SUM_ROW[sb + tid] / (CNT_ROW[(b << 10) + seg] + 1e-9f);
        else
            meanc[tid - 64] = SUM_COL[sb + (tid - 64)] / (CNT_COL[(b << 10) + seg] + 1e-9f);
        __syncthreads();
        const float* mean = isCol ? meanc : meanr;
        const float* M    = isCol ? Mc    : Mr;
        float acc = 0.f;
        #pragma unroll
        for (int f = 0; f < 64; ++f) acc += mean[f] * M[f * 64 + o];
        if (isCol) g_colvec[sb + o] = acc; else g_rowvec[sb + o] = acc;
        __syncthreads();
    }
}

// ---------------- K4: fused GEMV + gather + LReLU ----------------
// out[e] = lrelu(value[e] @ M_self + rowvec[i0] + colvec[i1] + biasb[b])
// Tile: 128 rows x 64 cols per 256-thread block; thread = 4 rows x 8 cols,
// inner product via packed fp32x2 FFMA2 (2x scalar FFMA throughput on sm_103a).
#define SMEM_MAIN ((128*68 + 4096)*4 + 256*4)
__global__ void __launch_bounds__(256) main_kernel(const float* __restrict__ value,
                                                   const int* __restrict__ index,
                                                   float* __restrict__ out) {
    extern __shared__ float sm[];
    float* Vs = sm;                 // [128][68] padded value tile
    float* Ms = sm + 128 * 68;      // [64][64] M_self
    int*   Is = (int*)(Ms + 4096);  // [128][2] indices
    const int tid = threadIdx.x;
    const long long base = (long long)blockIdx.x * 128;
    const int b = (int)(base >> 18);

    { // stage M_self
        const float4* Mg = (const float4*)g_M;
        float4* Md = (float4*)Ms;
        #pragma unroll
        for (int i = 0; i < 4; ++i) Md[tid + i * 256] = Mg[tid + i * 256];
    }
    { // stage value tile (coalesced float4), pad-68 rows
        const float4* Vg = (const float4*)(value + (base << 6));
        #pragma unroll
        for (int i = 0; i < 8; ++i) {
            const int li = tid + i * 256;    // float4 idx 0..2047
            const float4 v = Vg[li];
            const int L = li << 2;
            const int r = L >> 6, c = L & 63;
            *(float4*)(Vs + r * 68 + c) = v;
        }
    }
    if (tid < 128) {
        const int2 p = ((const int2*)index)[base + tid];
        Is[2 * tid] = p.x; Is[2 * tid + 1] = p.y;
    }
    __syncthreads();

    const int tx = tid & 7, ty = tid >> 3;
    const int o0 = tx << 3;     // 8 output cols
    const int r0 = ty << 2;     // 4 rows

    unsigned long long acc[4][4];
    #pragma unroll
    for (int j = 0; j < 4; ++j)
        #pragma unroll
        for (int p = 0; p < 4; ++p) acc[j][p] = 0ull;

    #pragma unroll 8
    for (int k = 0; k < 64; ++k) {
        const ulonglong2 mA = *(const ulonglong2*)(Ms + k * 64 + o0);      // m0..m3 as 2x f32x2
        const ulonglong2 mB = *(const ulonglong2*)(Ms + k * 64 + o0 + 4);  // m4..m7
        #pragma unroll
        for (int j = 0; j < 4; ++j) {
            const unsigned long long a = pk2(Vs[(r0 + j) * 68 + k]);
            fma2(acc[j][0], a, mA.x);
            fma2(acc[j][1], a, mA.y);
            fma2(acc[j][2], a, mB.x);
            fma2(acc[j][3], a, mB.y);
        }
    }

    const float4 bb0 = *(const float4*)(g_biasb + b * 64 + o0);
    const float4 bb1 = *(const float4*)(g_biasb + b * 64 + o0 + 4);
    #pragma unroll
    for (int j = 0; j < 4; ++j) {
        const int r = r0 + j;
        const int i0 = Is[2 * r], i1 = Is[2 * r + 1];
        const float* rv = g_rowvec + ((((long long)b << 10) + i0) << 6) + o0;
        const float* cv = g_colvec + ((((long long)b << 10) + i1) << 6) + o0;
        const float4 R0 = *(const float4*)rv,       R1 = *(const float4*)(rv + 4);
        const float4 C0 = *(const float4*)cv,       C1 = *(const float4*)(cv + 4);
        const float2 a0 = up2(acc[j][0]), a1 = up2(acc[j][1]);
        const float2 a2 = up2(acc[j][2]), a3 = up2(acc[j][3]);
        float o_[8] = { a0.x + R0.x + C0.x + bb0.x,
                        a0.y + R0.y + C0.y + bb0.y,
                        a1.x + R0.z + C0.z + bb0.z,
                        a1.y + R0.w + C0.w + bb0.w,
                        a2.x + R1.x + C1.x + bb1.x,
                        a2.y + R1.y + C1.y + bb1.y,
                        a3.x + R1.z + C1.z + bb1.z,
                        a3.y + R1.w + C1.w + bb1.w };
        #pragma unroll
        for (int q = 0; q < 8; ++q) o_[q] = fmaxf(o_[q], 0.01f * o_[q]);  // leaky relu
        float* op = out + ((base + r) << 6) + o0;
        *(float4*)op       = make_float4(o_[0], o_[1], o_[2], o_[3]);
        *(float4*)(op + 4) = make_float4(o_[4], o_[5], o_[6], o_[7]);
    }
}

// ---------------- index pass-through (tuple output (index, out)) ----------------
__global__ void idxcopy_kernel(const int* __restrict__ idx, float* __restrict__ out, int n4) {
    const int i = blockIdx.x * blockDim.x + threadIdx.x;
    if (i < n4) {
        const int4 v = ((const int4*)idx)[i];
        ((float4*)out)[i] = make_float4((float)v.x, (float)v.y, (float)v.z, (float)v.w);
    }
}

// ---------------- launch ----------------
extern "C" void kernel_launch(void* const* d_in, const int* in_sizes, int n_in,
                              void* d_out, int out_size) {
    const int*   index = (const int*)d_in[0];
    const float* value = (const float*)d_in[1];
    const float* Wself = (const float*)d_in[2];
    const float* bself = (const float*)d_in[3];
    const float* Wrow  = (const float*)d_in[4];
    const float* brow  = (const float*)d_in[5];
    const float* Wcol  = (const float*)d_in[6];
    const float* bcol  = (const float*)d_in[7];
    const float* Wglob = (const float*)d_in[8];
    const float* bglob = (const float*)d_in[9];
    const float* Wout  = (const float*)d_in[10];
    const float* bout  = (const float*)d_in[11];
    float* out = (float*)d_out;

    const long long main_elems = (long long)B_ * N_ * OUT_;
    const long long off = (long long)out_size - main_elems;
    float* out_main = (off > 0) ? (out + off) : out;

    void* accp = nullptr;
    cudaGetSymbolAddress(&accp, g_accum);
    cudaMemsetAsync(accp, 0, sizeof(float) * ACCUM_SZ, 0);

    cudaFuncSetAttribute(main_kernel, cudaFuncAttributeMaxDynamicSharedMemorySize, SMEM_MAIN);

    prep_kernel<<<64, 256>>>(Wself, Wrow, Wcol, Wglob, Wout, bself, brow, bcol, bglob, bout);
    scatter_kernel<<<(B_ * N_) / 256, 256>>>(value, index);
    gbias_kernel<<<B_, 64>>>();
    segvec_kernel<<<B_ * 32, 128>>>();
    main_kernel<<<(B_ * N_) / 128, 256, SMEM_MAIN>>>(value, index, out_main);

    if (off > 0) {
        const int n4 = (int)(off / 4);
        idxcopy_kernel<<<(n4 + 255) / 256, 256>>>(index, out, n4);
    }
}